// round 6
// baseline (speedup 1.0000x reference)
#include <cuda_runtime.h>
#include <stdint.h>

// Row layout: segments (u,v) = (128,1),(64,3),(32,5),(16,7), total 592 fp32.
// out[off + a*u + b] = in[off + b*v + a]
// Segment (128,1) is an identity copy -> bypass smem entirely for c in [0,128).
// Permuted part: c in [128,592), 464 floats per row staged in smem.
// For output column c: a=(c-off)>>log2(u), b=(c-off)&(u-1); src = off + b*v + a

#define ROW_DIM 592
#define ID_DIM 128                                // identity prefix
#define PM_DIM (ROW_DIM - ID_DIM)                 // 464 permuted floats
#define RPB 4                                     // rows per block
#define NT 128                                    // threads per block
#define ID_VEC4_PER_ROW (ID_DIM / 4)              // 32
#define PM_VEC4_PER_ROW (PM_DIM / 4)              // 116
#define ID_VEC4 (ID_VEC4_PER_ROW * RPB)           // 128
#define PM_VEC4 (PM_VEC4_PER_ROW * RPB)           // 464

// perm_src for c in [128, 592): source column within the row
__device__ __forceinline__ int perm_src_pm(int c) {
    if (c < 320) { int l = c - 128; return 128 + (l & 63) * 3 + (l >> 6); }
    if (c < 480) { int l = c - 320; return 320 + (l & 31) * 5 + (l >> 5); }
    { int l = c - 480; return 480 + (l & 15) * 7 + (l >> 4); }
}

__global__ __launch_bounds__(NT, 16)
void transpose_irreps_idbypass(const float* __restrict__ in, float* __restrict__ out) {
    // staged permuted part only: PM_DIM floats per row
    __shared__ __align__(16) float smem[RPB * PM_DIM];

    const int tid = threadIdx.x;
    const long long base = (long long)blockIdx.x * (ROW_DIM * RPB);
    const float* __restrict__ ib = in + base;
    float* __restrict__ ob = out + base;

    // Phase 1a: identity segment — direct register copy, no smem, no barrier.
    // One float4 per thread per row (NT=128 threads, 32 groups/row * 4 rows = 128).
    {
        int r = tid >> 5;                  // 0..3
        int g = tid & 31;                  // 0..31 float4 group within identity prefix
        const float4* s = reinterpret_cast<const float4*>(ib + r * ROW_DIM) + g;
        float4* d = reinterpret_cast<float4*>(ob + r * ROW_DIM) + g;
        float4 v = __ldcs(s);
        __stcs(d, v);
    }

    // Phase 1b: load permuted part (464 floats per row) into smem, vectorized.
    #pragma unroll
    for (int i = tid; i < PM_VEC4; i += NT) {
        int r = i / PM_VEC4_PER_ROW;                   // const divide
        int g = i - r * PM_VEC4_PER_ROW;               // float4 group in permuted part
        const float4* s = reinterpret_cast<const float4*>(ib + r * ROW_DIM + ID_DIM) + g;
        reinterpret_cast<float4*>(smem + r * PM_DIM)[g] = __ldcs(s);
    }
    __syncthreads();

    // Phase 2: permuted stores. Lane-consecutive output c -> coalesced STG.32;
    // smem gather lane-stride = v in {3,5,7} (odd) -> conflict-free.
    #pragma unroll
    for (int cb = 0; cb < PM_DIM; cb += NT) {
        int c = cb + tid;
        if (c < PM_DIM) {
            int s = perm_src_pm(c + ID_DIM) - ID_DIM;  // index within staged part
            #pragma unroll
            for (int r = 0; r < RPB; r++) {
                __stcs(ob + r * ROW_DIM + ID_DIM + c, smem[r * PM_DIM + s]);
            }
        }
    }
}

extern "C" void kernel_launch(void* const* d_in, const int* in_sizes, int n_in,
                              void* d_out, int out_size) {
    const float* x = (const float*)d_in[0];
    float* out = (float*)d_out;
    int n_rows = in_sizes[0] / ROW_DIM;     // 200000
    int grid = n_rows / RPB;                // 50000 (exact)
    transpose_irreps_idbypass<<<grid, NT>>>(x, out);
}